// round 1
// baseline (speedup 1.0000x reference)
#include <cuda_runtime.h>

// Problem constants
#define E_  16
#define B_  4096
#define DX_ 128
#define DC_ 64
#define DIN_ 192
#define DH_ 1024
#define DO_ 128

#define BM 64          // rows of B per block
#define CHUNK 64       // DH chunk size
#define NCHUNK (DH_ / CHUNK)
#define THREADS 256

// padded smem strides (floats). 76 % 4 == 0 (float4 aligned), 76 % 32 == 12 -> 4-way write conflicts only.
#define SXT 76         // row stride for s_xc / s_w1 / s_h (64 cols + pad)
#define SW2 132        // row stride for s_w2 (128 cols + pad)

// smem layout (floats):
//  s_xc : [DIN][SXT]   transposed xc tile     (192*76)
//  s_w1 : [DIN][SXT]   transposed W1 chunk    (192*76)
//  s_h  : [CHUNK][SXT] transposed h chunk     (64*76)
//  s_w2 : [CHUNK][SW2] transposed W2 chunk    (64*132)
#define SMEM_FLOATS (DIN_*SXT*2 + CHUNK*SXT + CHUNK*SW2)
#define SMEM_BYTES  (SMEM_FLOATS * 4)

__global__ __launch_bounds__(THREADS, 1)
void expert_mlp_fused_kernel(const float* __restrict__ x,
                             const float* __restrict__ cond,
                             const float* __restrict__ W1,
                             const float* __restrict__ b1,
                             const float* __restrict__ W2,
                             const float* __restrict__ b2,
                             float* __restrict__ out)
{
    extern __shared__ float smem[];
    float* s_xc = smem;                    // [192][76]
    float* s_w1 = s_xc + DIN_ * SXT;       // [192][76]
    float* s_h  = s_w1 + DIN_ * SXT;       // [64][76]
    float* s_w2 = s_h  + CHUNK * SXT;      // [64][132]

    const int tid = threadIdx.x;
    const int tx = tid & 15;               // 0..15 -> columns
    const int ty = tid >> 4;               // 0..15 -> rows

    const int blocks_per_e = B_ / BM;      // 64
    const int e  = blockIdx.x / blocks_per_e;
    const int m0 = (blockIdx.x % blocks_per_e) * BM;

    const float* xp  = x    + (size_t)e * B_ * DX_ + (size_t)m0 * DX_;
    const float* cp  = cond + (size_t)e * B_ * DC_ + (size_t)m0 * DC_;
    const float* w1p = W1   + (size_t)e * DH_ * DIN_;
    const float* w2p = W2   + (size_t)e * DO_ * DH_;
    const float* b1p = b1   + (size_t)e * DH_;
    const float* b2p = b2   + (size_t)e * DO_;
    float*       op  = out  + (size_t)e * B_ * DO_ + (size_t)m0 * DO_;

    // ---- stage xc tile, transposed: s_xc[k][row] ----
    // consecutive tid -> consecutive k -> coalesced global reads
    for (int idx = tid; idx < BM * DIN_; idx += THREADS) {
        const int row = idx / DIN_;
        const int k   = idx % DIN_;
        const float v = (k < DX_) ? xp[row * DX_ + k]
                                  : cp[row * DC_ + (k - DX_)];
        s_xc[k * SXT + row] = v;
    }

    // y accumulators: 4 rows (4*ty+i) x 8 cols (8*tx+j)
    float acc[4][8];
    #pragma unroll
    for (int i = 0; i < 4; i++)
        #pragma unroll
        for (int j = 0; j < 8; j++)
            acc[i][j] = 0.0f;

    __syncthreads();   // xc staged (also covers first chunk's weight staging below)

    for (int ch = 0; ch < NCHUNK; ch++) {
        const int dh0 = ch * CHUNK;

        // ---- stage W1 chunk, transposed: s_w1[k][c], c = local dh ----
        for (int idx = tid; idx < CHUNK * DIN_; idx += THREADS) {
            const int c = idx / DIN_;
            const int k = idx % DIN_;
            s_w1[k * SXT + c] = w1p[(dh0 + c) * DIN_ + k];
        }
        // ---- stage W2 chunk, transposed: s_w2[kk][c], c = output col ----
        for (int idx = tid; idx < DO_ * CHUNK; idx += THREADS) {
            const int c  = idx >> 6;       // /64
            const int kk = idx & 63;
            s_w2[kk * SW2 + c] = w2p[c * DH_ + dh0 + kk];
        }
        __syncthreads();

        // ---- h-GEMM: h[4ty+i][4tx+j] over K=192 ----
        float hacc[4][4];
        #pragma unroll
        for (int i = 0; i < 4; i++)
            #pragma unroll
            for (int j = 0; j < 4; j++)
                hacc[i][j] = 0.0f;

        #pragma unroll 4
        for (int k = 0; k < DIN_; k++) {
            const float4 a = *(const float4*)(s_xc + k * SXT + 4 * ty);
            const float4 w = *(const float4*)(s_w1 + k * SXT + 4 * tx);
            const float av[4] = {a.x, a.y, a.z, a.w};
            const float wv[4] = {w.x, w.y, w.z, w.w};
            #pragma unroll
            for (int i = 0; i < 4; i++)
                #pragma unroll
                for (int j = 0; j < 4; j++)
                    hacc[i][j] += av[i] * wv[j];
        }

        // bias + relu, store transposed: s_h[c][row]
        const float4 b1v = *(const float4*)(b1p + dh0 + 4 * tx);
        const float bv[4] = {b1v.x, b1v.y, b1v.z, b1v.w};
        #pragma unroll
        for (int j = 0; j < 4; j++) {
            float4 hv;
            hv.x = fmaxf(hacc[0][j] + bv[j], 0.0f);
            hv.y = fmaxf(hacc[1][j] + bv[j], 0.0f);
            hv.z = fmaxf(hacc[2][j] + bv[j], 0.0f);
            hv.w = fmaxf(hacc[3][j] + bv[j], 0.0f);
            *(float4*)(s_h + (4 * tx + j) * SXT + 4 * ty) = hv;
        }
        __syncthreads();

        // ---- y-GEMM: acc[i][j] += h[4ty+i][kk] * W2[8tx+j][kk], K=64 ----
        #pragma unroll 4
        for (int kk = 0; kk < CHUNK; kk++) {
            const float4 a  = *(const float4*)(s_h  + kk * SXT + 4 * ty);
            const float4 w0 = *(const float4*)(s_w2 + kk * SW2 + 8 * tx);
            const float4 w1v = *(const float4*)(s_w2 + kk * SW2 + 8 * tx + 4);
            const float av[4] = {a.x, a.y, a.z, a.w};
            const float wv[8] = {w0.x, w0.y, w0.z, w0.w, w1v.x, w1v.y, w1v.z, w1v.w};
            #pragma unroll
            for (int i = 0; i < 4; i++)
                #pragma unroll
                for (int j = 0; j < 8; j++)
                    acc[i][j] += av[i] * wv[j];
        }
        __syncthreads();   // protect s_w1/s_w2/s_h before next chunk's staging
    }

    // ---- epilogue: + b2, write out ----
    const float4 b2lo = *(const float4*)(b2p + 8 * tx);
    const float4 b2hi = *(const float4*)(b2p + 8 * tx + 4);
    #pragma unroll
    for (int i = 0; i < 4; i++) {
        const int row = 4 * ty + i;
        float4 o0, o1;
        o0.x = acc[i][0] + b2lo.x; o0.y = acc[i][1] + b2lo.y;
        o0.z = acc[i][2] + b2lo.z; o0.w = acc[i][3] + b2lo.w;
        o1.x = acc[i][4] + b2hi.x; o1.y = acc[i][5] + b2hi.y;
        o1.z = acc[i][6] + b2hi.z; o1.w = acc[i][7] + b2hi.w;
        *(float4*)(op + row * DO_ + 8 * tx)     = o0;
        *(float4*)(op + row * DO_ + 8 * tx + 4) = o1;
    }
}

extern "C" void kernel_launch(void* const* d_in, const int* in_sizes, int n_in,
                              void* d_out, int out_size)
{
    const float* x    = (const float*)d_in[0];
    const float* cond = (const float*)d_in[1];
    const float* W1   = (const float*)d_in[2];
    const float* b1   = (const float*)d_in[3];
    const float* W2   = (const float*)d_in[4];
    const float* b2   = (const float*)d_in[5];
    float* out = (float*)d_out;

    cudaFuncSetAttribute(expert_mlp_fused_kernel,
                         cudaFuncAttributeMaxDynamicSharedMemorySize, SMEM_BYTES);

    const int grid = E_ * (B_ / BM);   // 1024 blocks
    expert_mlp_fused_kernel<<<grid, THREADS, SMEM_BYTES>>>(x, cond, W1, b1, W2, b2, out);
}

// round 3
// speedup vs baseline: 5.6838x; 5.6838x over previous
#include <cuda_runtime.h>
#include <cstdint>

// ---------------- problem constants ----------------
#define E_   16
#define B_   4096
#define DX_  128
#define DC_  64
#define DIN_ 192
#define DH_  1024
#define DO_  128

#define BM   128            // batch rows per CTA
#define CHN  32             // DH chunk
#define NCH  (DH_/CHN)      // 32 chunks
#define THREADS 256

// ---------------- smem strides (floats), all == 4 (mod 32) for conflict-free frags
#define SXC 196   // xc  [128][196]  (k = 0..191)
#define SW1 196   // W1  [32 rows n][196] (k = 0..191), double-buffered
#define SW2 36    // W2  [128 rows n][36] (k = 0..31), double-buffered
#define SH  36    // h   [128][36]   (k = 0..31)

// smem offsets in floats
#define OFF_XC 0
#define N_XC   (BM*SXC)                 // 25088
#define OFF_W1 (OFF_XC + N_XC)          // 25088
#define N_W1   (CHN*SW1)                // 6272 per buf
#define OFF_W2 (OFF_W1 + 2*N_W1)        // 37632
#define N_W2   (DO_*SW2)                // 4608 per buf
#define OFF_H  (OFF_W2 + 2*N_W2)        // 46848
#define N_H    (BM*SH)                  // 4608
#define OFF_B1 (OFF_H + N_H)            // 51456
#define OFF_B2 (OFF_B1 + DH_)           // 52480
#define SMEM_FLOATS (OFF_B2 + DO_)      // 52608
#define SMEM_BYTES  (SMEM_FLOATS*4)     // 210432

// ---------------- helpers ----------------
__device__ __forceinline__ uint32_t s2u(const void* p){
    uint32_t a;
    asm("{ .reg .u64 t; cvta.to.shared.u64 t, %1; cvt.u32.u64 %0, t; }" : "=r"(a) : "l"(p));
    return a;
}
__device__ __forceinline__ uint32_t f2tf32(float f){
    uint32_t u; asm("cvt.rna.tf32.f32 %0, %1;" : "=r"(u) : "f"(f)); return u;
}
__device__ __forceinline__ float tf32relu(float v){
    float r = fmaxf(v, 0.0f);
    uint32_t u; asm("cvt.rna.tf32.f32 %0, %1;" : "=r"(u) : "f"(r));
    return __uint_as_float(u);
}
__device__ __forceinline__ void cp16(uint32_t dst, const void* src){
    asm volatile("cp.async.cg.shared.global [%0], [%1], 16;" :: "r"(dst), "l"(src) : "memory");
}
#define CP_COMMIT() asm volatile("cp.async.commit_group;" ::: "memory")
#define CP_WAIT0()  asm volatile("cp.async.wait_group 0;" ::: "memory")

__device__ __forceinline__ void mma_tf32(float c[4],
                                         uint32_t a0, uint32_t a1, uint32_t a2, uint32_t a3,
                                         uint32_t b0, uint32_t b1){
    asm volatile(
        "mma.sync.aligned.m16n8k8.row.col.f32.tf32.tf32.f32 "
        "{%0,%1,%2,%3}, {%4,%5,%6,%7}, {%8,%9}, {%0,%1,%2,%3};"
        : "+f"(c[0]), "+f"(c[1]), "+f"(c[2]), "+f"(c[3])
        : "r"(a0), "r"(a1), "r"(a2), "r"(a3), "r"(b0), "r"(b1));
}

// stage one DH chunk of W1 + W2 into smem buffer `buf` via cp.async
__device__ __forceinline__ void stage_w(uint32_t sb, const float* __restrict__ w1p,
                                        const float* __restrict__ w2p, int ch, int buf, int tid)
{
    // W1 rows [ch*32, ch*32+32), each 192 floats = 48 x 16B
    const float* w1src = w1p + (size_t)ch * CHN * DIN_;
    const uint32_t w1b = sb + (OFF_W1 + buf * N_W1) * 4;
    #pragma unroll
    for (int i = tid; i < CHN * 48; i += THREADS) {
        const int r = i / 48, j = i % 48;
        cp16(w1b + r * (SW1*4) + j * 16, w1src + r * DIN_ + j * 4);
    }
    // W2: 128 rows, k-window [ch*32, +32) = 8 x 16B per row
    const uint32_t w2b = sb + (OFF_W2 + buf * N_W2) * 4;
    #pragma unroll
    for (int i = tid; i < DO_ * 8; i += THREADS) {
        const int r = i / 8, j = i % 8;
        cp16(w2b + r * (SW2*4) + j * 16, w2p + (size_t)r * DH_ + ch * CHN + j * 4);
    }
}

// ---------------- kernel ----------------
__global__ __launch_bounds__(THREADS, 1)
void expert_mlp_hmma_kernel(const float* __restrict__ x, const float* __restrict__ cond,
                            const float* __restrict__ W1, const float* __restrict__ b1,
                            const float* __restrict__ W2, const float* __restrict__ b2,
                            float* __restrict__ out)
{
    extern __shared__ float sm[];
    float* s_xc = sm + OFF_XC;
    float* s_h  = sm + OFF_H;
    float* s_b1 = sm + OFF_B1;
    float* s_b2 = sm + OFF_B2;
    const uint32_t sb = s2u(sm);

    const int tid  = threadIdx.x;
    const int lane = tid & 31;
    const int wid  = tid >> 5;
    const int gr   = lane >> 2;     // group row / n-col within fragment
    const int ct   = lane & 3;      // k-offset within fragment
    const int mw   = wid & 3;       // warp M index (4)
    const int nw   = wid >> 2;      // warp N index (2)

    const int e  = blockIdx.x >> 5;           // 32 CTAs per expert
    const int m0 = (blockIdx.x & 31) * BM;

    const float* xp  = x    + (size_t)e * B_ * DX_ + (size_t)m0 * DX_;
    const float* cp_ = cond + (size_t)e * B_ * DC_ + (size_t)m0 * DC_;
    const float* w1p = W1   + (size_t)e * DH_ * DIN_;
    const float* w2p = W2   + (size_t)e * DO_ * DH_;
    float*       op  = out  + (size_t)e * B_ * DO_ + (size_t)m0 * DO_;

    // biases (once)
    {
        const float4 v = *(const float4*)(b1 + (size_t)e * DH_ + tid * 4);
        *(float4*)(s_b1 + tid * 4) = v;
        if (tid < 32) {
            const float4 w = *(const float4*)(b2 + (size_t)e * DO_ + tid * 4);
            *(float4*)(s_b2 + tid * 4) = w;
        }
    }

    // stage xc tile (rows = batch, 192 floats per padded row of 196)
    #pragma unroll
    for (int i = tid; i < BM * 48; i += THREADS) {
        const int r = i / 48, j = i % 48;
        const uint32_t dst = sb + (OFF_XC + r * SXC) * 4 + ((j < 32) ? j * 16 : 512 + (j - 32) * 16);
        const float* src = (j < 32) ? (xp + (size_t)r * DX_ + j * 4)
                                    : (cp_ + (size_t)r * DC_ + (j - 32) * 4);
        cp16(dst, src);
    }
    stage_w(sb, w1p, w2p, 0, 0, tid);
    CP_COMMIT();
    CP_WAIT0();
    __syncthreads();

    // y accumulators: warp tile 32 x 64 -> 2 Mtiles x 8 Ntiles x 4 regs
    float yacc[2][8][4];
    #pragma unroll
    for (int a = 0; a < 2; a++)
        #pragma unroll
        for (int b = 0; b < 8; b++)
            #pragma unroll
            for (int c = 0; c < 4; c++) yacc[a][b][c] = 0.0f;

    for (int ch = 0; ch < NCH; ++ch) {
        const int buf = ch & 1;

        // prefetch next chunk's weights (overlaps with compute)
        if (ch + 1 < NCH) stage_w(sb, w1p, w2p, ch + 1, buf ^ 1, tid);
        CP_COMMIT();

        // ---- MMA1: h[128x32] = xc[128x192] @ W1chunk^T ----
        const float* w1s = sm + OFF_W1 + buf * N_W1;
        float hacc[2][2][4];
        #pragma unroll
        for (int a = 0; a < 2; a++)
            #pragma unroll
            for (int b = 0; b < 2; b++)
                #pragma unroll
                for (int c = 0; c < 4; c++) hacc[a][b][c] = 0.0f;

        #pragma unroll
        for (int kt = 0; kt < DIN_ / 8; ++kt) {
            const int k0 = kt * 8;
            uint32_t A[2][4], Bf[2][2];
            #pragma unroll
            for (int tm = 0; tm < 2; ++tm) {
                const int row = mw * 32 + tm * 16 + gr;
                const float* p = s_xc + row * SXC + k0 + ct;
                A[tm][0] = f2tf32(p[0]);
                A[tm][1] = f2tf32(p[8 * SXC]);
                A[tm][2] = f2tf32(p[4]);
                A[tm][3] = f2tf32(p[8 * SXC + 4]);
            }
            #pragma unroll
            for (int tn = 0; tn < 2; ++tn) {
                const int n = nw * 16 + tn * 8 + gr;
                const float* p = w1s + n * SW1 + k0 + ct;
                Bf[tn][0] = f2tf32(p[0]);
                Bf[tn][1] = f2tf32(p[4]);
            }
            #pragma unroll
            for (int tm = 0; tm < 2; ++tm)
                #pragma unroll
                for (int tn = 0; tn < 2; ++tn)
                    mma_tf32(hacc[tm][tn], A[tm][0], A[tm][1], A[tm][2], A[tm][3],
                             Bf[tn][0], Bf[tn][1]);
        }

        // ---- epilogue: relu(h + b1) -> tf32, store to s_h ----
        #pragma unroll
        for (int tn = 0; tn < 2; ++tn) {
            const int n0 = nw * 16 + tn * 8 + 2 * ct;      // local col in chunk (even)
            const float bb0 = s_b1[ch * CHN + n0];
            const float bb1 = s_b1[ch * CHN + n0 + 1];
            #pragma unroll
            for (int tm = 0; tm < 2; ++tm) {
                const int row = mw * 32 + tm * 16 + gr;
                float2 lo, hi;
                lo.x = tf32relu(hacc[tm][tn][0] + bb0);
                lo.y = tf32relu(hacc[tm][tn][1] + bb1);
                hi.x = tf32relu(hacc[tm][tn][2] + bb0);
                hi.y = tf32relu(hacc[tm][tn][3] + bb1);
                *(float2*)(s_h + row * SH + n0)       = lo;
                *(float2*)(s_h + (row + 8) * SH + n0) = hi;
            }
        }
        __syncthreads();   // h visible to all warps

        // ---- MMA2: y[128x128] += h[128x32] @ W2chunk^T ----
        const float* w2s = sm + OFF_W2 + buf * N_W2;
        #pragma unroll
        for (int kt = 0; kt < CHN / 8; ++kt) {
            const int k0 = kt * 8;
            uint32_t A[2][4], Bf[8][2];
            #pragma unroll
            for (int tm = 0; tm < 2; ++tm) {
                const int row = mw * 32 + tm * 16 + gr;
                const uint32_t* p = (const uint32_t*)(s_h + row * SH + k0 + ct);
                A[tm][0] = p[0];                      // already tf32 bit patterns
                A[tm][1] = p[8 * SH];
                A[tm][2] = p[4];
                A[tm][3] = p[8 * SH + 4];
            }
            #pragma unroll
            for (int tn = 0; tn < 8; ++tn) {
                const int n = nw * 64 + tn * 8 + gr;
                const float* p = w2s + n * SW2 + k0 + ct;
                Bf[tn][0] = f2tf32(p[0]);
                Bf[tn][1] = f2tf32(p[4]);
            }
            #pragma unroll
            for (int tm = 0; tm < 2; ++tm)
                #pragma unroll
                for (int tn = 0; tn < 8; ++tn)
                    mma_tf32(yacc[tm][tn], A[tm][0], A[tm][1], A[tm][2], A[tm][3],
                             Bf[tn][0], Bf[tn][1]);
        }

        CP_WAIT0();        // next chunk's weights landed
        __syncthreads();   // also: all MMA2 h-reads done before next epilogue overwrites s_h
    }

    // ---- final epilogue: y + b2 -> gmem ----
    #pragma unroll
    for (int tn = 0; tn < 8; ++tn) {
        const int col = nw * 64 + tn * 8 + 2 * ct;
        const float bb0 = s_b2[col];
        const float bb1 = s_b2[col + 1];
        #pragma unroll
        for (int tm = 0; tm < 2; ++tm) {
            const int row = mw * 32 + tm * 16 + gr;
            float2 lo, hi;
            lo.x = yacc[tm][tn][0] + bb0;
            lo.y = yacc[tm][tn][1] + bb1;
            hi.x = yacc[tm][tn][2] + bb0;
            hi.y = yacc[tm][tn][3] + bb1;
            *(float2*)(op + (size_t)row * DO_ + col)       = lo;
            *(float2*)(op + (size_t)(row + 8) * DO_ + col) = hi;
        }
    }
}

extern "C" void kernel_launch(void* const* d_in, const int* in_sizes, int n_in,
                              void* d_out, int out_size)
{
    const float* x    = (const float*)d_in[0];
    const float* cond = (const float*)d_in[1];
    const float* W1   = (const float*)d_in[2];
    const float* b1   = (const float*)d_in[3];
    const float* W2   = (const float*)d_in[4];
    const float* b2   = (const float*)d_in[5];
    float* out = (float*)d_out;

    cudaFuncSetAttribute(expert_mlp_hmma_kernel,
                         cudaFuncAttributeMaxDynamicSharedMemorySize, SMEM_BYTES);

    const int grid = E_ * (B_ / BM);   // 512 CTAs
    expert_mlp_hmma_kernel<<<grid, THREADS, SMEM_BYTES>>>(x, cond, W1, b1, W2, b2, out);
}